// round 12
// baseline (speedup 1.0000x reference)
#include <cuda_runtime.h>

#define B_   128
#define C_   1024
#define HW_  256
#define S_   32
#define EMB_ 256
#define TC   128    // channels per block (kernel 2)
#define PC   16     // p-rows per smem chunk (kernel 2)
#define NCHUNK (HW_ / PC)   // 16

typedef unsigned long long u64;

// ---- packed f32x2 helpers (sm_103a FFMA2 path) ----
__device__ __forceinline__ u64 pk2(float x, float y) {
  u64 r; asm("mov.b64 %0, {%1, %2};" : "=l"(r) : "f"(x), "f"(y)); return r;
}
__device__ __forceinline__ void upk2(u64 v, float& x, float& y) {
  asm("mov.b64 {%0, %1}, %2;" : "=f"(x), "=f"(y) : "l"(v));
}
__device__ __forceinline__ void fma2(u64& d, u64 a, u64 b) {   // d += a*b (2 lanes)
  asm("fma.rn.f32x2 %0, %1, %2, %0;" : "+l"(d) : "l"(a), "l"(b));
}
__device__ __forceinline__ u64 add2(u64 a, u64 b) {
  u64 r; asm("add.rn.f32x2 %0, %1, %2;" : "=l"(r) : "l"(a), "l"(b)); return r;
}

// we transposed: [b][p][s], 4 MB scratch
__device__ float g_we[(size_t)B_ * HW_ * S_];

// ---------------------------------------------------------------------------
// Kernel 1: we_t[b][p][s] = sum_e word_emb[b][s][e] * ck[e][p] + bias[p]
// Grid (4, B). Coalesced transpose: lane = s, float4 along e, conflict-free STS.
// ---------------------------------------------------------------------------
__global__ __launch_bounds__(256) void we_proj_kernel(
    const float* __restrict__ word_emb,
    const float* __restrict__ ck,
    const float* __restrict__ bias) {
  __shared__ __align__(16) float smem_pool[EMB_ * S_];   // 32 KB
  float (*emb_t)[S_] = (float (*)[S_])smem_pool;          // [e][s]
  u64 (*red)[64][19]  = (u64 (*)[64][19])smem_pool;       // [3][64][19] u64, aliased

  const int b  = blockIdx.y;
  const int ph = blockIdx.x;        // p-quarter 0..3
  const int t  = threadIdx.x;

  const float* wb = word_emb + (size_t)b * S_ * EMB_;
  // transpose-load: lane = s; float4 read along e (16B per lane), STS conflict-free
  {
    const int lane = t & 31;        // = s
    const int w    = t >> 5;        // warp id 0..7
#pragma unroll
    for (int k = 0; k < 8; k++) {
      const int e0 = w * 4 + k * 32;
      float4 v = *(const float4*)&wb[lane * EMB_ + e0];
      emb_t[e0 + 0][lane] = v.x;
      emb_t[e0 + 1][lane] = v.y;
      emb_t[e0 + 2][lane] = v.z;
      emb_t[e0 + 3][lane] = v.w;
    }
  }
  __syncthreads();

  const int p_loc = t & 63;
  const int p     = ph * 64 + p_loc;
  const int eh    = t >> 6;         // e-slice 0..3

  u64 acc2[S_ / 2];
  {
    const u64 init = (eh == 0) ? pk2(bias[p], bias[p]) : 0ull;
#pragma unroll
    for (int q = 0; q < S_ / 2; q++) acc2[q] = init;
  }

#pragma unroll 4
  for (int i = 0; i < EMB_ / 4; i++) {
    const int e = eh * 64 + i;
    const float ckv = ck[e * EMB_ + p];       // coalesced, L2-resident
    const u64 c2 = pk2(ckv, ckv);
    const ulonglong2* er = (const ulonglong2*)emb_t[e];
#pragma unroll
    for (int q = 0; q < 8; q++) {
      ulonglong2 v = er[q];
      fma2(acc2[2*q + 0], v.x, c2);
      fma2(acc2[2*q + 1], v.y, c2);
    }
  }
  __syncthreads();   // all emb_t reads done before red aliases the pool

  if (eh > 0) {
#pragma unroll
    for (int q = 0; q < S_ / 2; q++) red[eh - 1][p_loc][q] = acc2[q];
  }
  __syncthreads();

  if (eh == 0) {
#pragma unroll
    for (int q = 0; q < S_ / 2; q++)
      acc2[q] = add2(add2(acc2[q], red[0][p_loc][q]),
                     add2(red[1][p_loc][q], red[2][p_loc][q]));
    ulonglong2* o = (ulonglong2*)(g_we + ((size_t)b * HW_ + p) * S_);
#pragma unroll
    for (int q = 0; q < 8; q++) {
      ulonglong2 v; v.x = acc2[2*q]; v.y = acc2[2*q + 1];
      o[q] = v;
    }
  }
}

// ---------------------------------------------------------------------------
// Kernel 2 (fused), TC=128, channel-packed f32x2 (zero per-iteration packs):
//   smem (dynamic, 80 KB): we_dup[256][32] u64 (64 KB) + 16 KB pool
//   logits: per pp: 1 LDS.128 wc (2 ch-pairs) + 2 LDS.128 we_dup + 8 FFMA2
//   softmax over s (8-lane shuffle groups), attn STG.128 from regs
//   epilogue: ch-pair accumulators -> direct STG.64, attn pairs via LDS.64
// ---------------------------------------------------------------------------
__global__ __launch_bounds__(256, 2) void attn_kernel(
    const float* __restrict__ wc,
    float* __restrict__ out,
    float* __restrict__ attn_out) {
  extern __shared__ __align__(16) char dsm[];
  u64 (*we_dup)[S_] = (u64 (*)[S_])dsm;                 // 64 KB: [p][s] duplicated
  float* pool = (float*)(dsm + (size_t)HW_ * S_ * 8);   // 16 KB
  float (*attn_t)[TC] = (float (*)[TC])pool;            // [s][c], after logits

  const int b  = blockIdx.y;
  const int c0 = blockIdx.x * TC;
  const int t  = threadIdx.x;

  // chunk-0 preload (issue LDG early, overlap with we staging)
  const float* wcb = wc + (size_t)b * HW_ * C_ + c0;
  const int ldrow = t >> 5;            // 0..7 (rows ldrow, ldrow+8)
  const int ldcol = (t & 31) << 2;     // 0,4,..,124
  const float* ldsrc0 = wcb + (size_t)ldrow * C_ + ldcol;
  const float* ldsrc1 = wcb + (size_t)(ldrow + 8) * C_ + ldcol;
  float4 pre0 = *(const float4*)ldsrc0;
  float4 pre1 = *(const float4*)ldsrc1;

  // stage we_t[b] into smem, duplicating each value into both f32x2 lanes
  {
    const float4* gw = (const float4*)(g_we + (size_t)b * HW_ * S_);
    u64* wd = (u64*)we_dup;
    for (int i = t; i < HW_ * S_ / 4; i += 256) {
      float4 v = gw[i];
      ulonglong2* d = (ulonglong2*)&wd[i * 4];
      ulonglong2 d0, d1;
      d0.x = pk2(v.x, v.x); d0.y = pk2(v.y, v.y);
      d1.x = pk2(v.z, v.z); d1.y = pk2(v.w, v.w);
      d[0] = d0; d[1] = d1;
    }
  }
  *(float4*)&pool[ldrow * TC + ldcol]        = pre0;
  *(float4*)&pool[(ldrow + 8) * TC + ldcol]  = pre1;
  __syncthreads();                     // chunk 0 + we_dup visible

  // ---- logits: thread owns channels 4cg..4cg+3 (2 pairs), s = 4sg..4sg+3 ----
  const int cg = t >> 3;   // 0..31
  const int sg = t & 7;    // 0..7
  u64 acc2[2][4];          // [ch-pair][s]: {c_even, c_odd} per scalar s
#pragma unroll
  for (int i = 0; i < 2; i++)
#pragma unroll
    for (int j = 0; j < 4; j++) acc2[i][j] = 0ull;

  for (int pcI = 0; pcI < NCHUNK; pcI++) {
    if (pcI + 1 < NCHUNK) {            // hide next chunk's LDG behind compute
      pre0 = *(const float4*)(ldsrc0 + (size_t)(pcI + 1) * PC * C_);
      pre1 = *(const float4*)(ldsrc1 + (size_t)(pcI + 1) * PC * C_);
    }
    const float* buf = pool + (pcI & 1) * (PC * TC);
#pragma unroll
    for (int pp = 0; pp < PC; pp++) {
      // 2 channel-pairs, already packed — no MOVs
      ulonglong2 w = *(const ulonglong2*)&buf[pp * TC + cg * 4];
      // 4 duplicated s-operands
      const ulonglong2* wr = (const ulonglong2*)&we_dup[pcI * PC + pp][sg * 4];
      ulonglong2 v0 = wr[0], v1 = wr[1];
      fma2(acc2[0][0], v0.x, w.x);  fma2(acc2[1][0], v0.x, w.y);
      fma2(acc2[0][1], v0.y, w.x);  fma2(acc2[1][1], v0.y, w.y);
      fma2(acc2[0][2], v1.x, w.x);  fma2(acc2[1][2], v1.x, w.y);
      fma2(acc2[0][3], v1.y, w.x);  fma2(acc2[1][3], v1.y, w.y);
    }
    if (pcI + 1 < NCHUNK) {
      float* nb = pool + ((pcI + 1) & 1) * (PC * TC);
      *(float4*)&nb[ldrow * TC + ldcol]       = pre0;
      *(float4*)&nb[(ldrow + 8) * TC + ldcol] = pre1;
    }
    __syncthreads();                   // one barrier per chunk
  }

  // unpack: av[i][j] = logit of channel 4cg+i at s = 4sg+j
  float av[4][4];
#pragma unroll
  for (int j = 0; j < 4; j++) {
    upk2(acc2[0][j], av[0][j], av[1][j]);
    upk2(acc2[1][j], av[2][j], av[3][j]);
  }

  // ---- softmax over s per channel (8-lane aligned shuffle groups) ----
#pragma unroll
  for (int i = 0; i < 4; i++) {
    float m = fmaxf(fmaxf(av[i][0], av[i][1]), fmaxf(av[i][2], av[i][3]));
#pragma unroll
    for (int o = 1; o < 8; o <<= 1) m = fmaxf(m, __shfl_xor_sync(0xffffffffu, m, o));
    float sum = 0.f;
#pragma unroll
    for (int j = 0; j < 4; j++) { av[i][j] = __expf(av[i][j] - m); sum += av[i][j]; }
#pragma unroll
    for (int o = 1; o < 8; o <<= 1) sum += __shfl_xor_sync(0xffffffffu, sum, o);
    const float inv = 1.f / sum;
#pragma unroll
    for (int j = 0; j < 4; j++) av[i][j] *= inv;
  }

  // ---- attn -> gmem straight from registers: attn[b][c][4sg..4sg+3] ----
  {
    float* ab = attn_out + ((size_t)b * C_ + c0 + cg * 4) * S_ + sg * 4;
#pragma unroll
    for (int i = 0; i < 4; i++)
      *(float4*)(ab + (size_t)i * S_) = make_float4(av[i][0], av[i][1], av[i][2], av[i][3]);
  }

  // ---- attn_t[s][c] into the (now dead) pool ----
#pragma unroll
  for (int j = 0; j < 4; j++)
    *(float4*)&attn_t[sg * 4 + j][cg * 4] =
        make_float4(av[0][j], av[1][j], av[2][j], av[3][j]);
  __syncthreads();

  // ---- epilogue: out[b][p][c0 + 2*cp, +1] = sum_s we[p][s] * attn[c][s] ----
  {
    const int cp = t & 63;             // channel pair: channels 2cp, 2cp+1
    const int pg = t >> 6;             // 0..3 -> 64 p each
    u64 ap[S_];                        // attn pairs per s: {attn[2cp][s], attn[2cp+1][s]}
#pragma unroll
    for (int s = 0; s < S_; s++)
      ap[s] = *(const u64*)&attn_t[s][cp * 2];   // LDS.64, 256B/warp contiguous

    float2* ob = (float2*)(out + (size_t)b * HW_ * C_ + c0 + cp * 2);
#pragma unroll 2
    for (int k = 0; k < 64; k++) {
      const int p = pg * 64 + k;
      const ulonglong2* wr = (const ulonglong2*)we_dup[p];  // broadcast row (dup)
      u64 ch[4];
#pragma unroll
      for (int q = 0; q < 4; q++) ch[q] = 0ull;
#pragma unroll
      for (int q = 0; q < 16; q++) {   // 16 x LDS.128 -> 32 dup s-values
        ulonglong2 v = wr[q];
        fma2(ch[q & 3], v.x, ap[2*q + 0]);
        fma2(ch[q & 3], v.y, ap[2*q + 1]);
      }
      u64 r = add2(add2(ch[0], ch[1]), add2(ch[2], ch[3]));
      float lo, hi;
      upk2(r, lo, hi);
      ob[(size_t)p * (C_ / 2)] = make_float2(lo, hi);   // STG.64, coalesced 256B/warp
    }
  }
}

// ---------------------------------------------------------------------------
extern "C" void kernel_launch(void* const* d_in, const int* in_sizes, int n_in,
                              void* d_out, int out_size) {
  const float* wc_in    = (const float*)d_in[0];  // weighted_context [128,16,16,1024]
  const float* word_emb = (const float*)d_in[1];  // [128,32,256]
  const float* ck       = (const float*)d_in[2];  // [256,256]
  const float* bias     = (const float*)d_in[3];  // [256]

  float* out  = (float*)d_out;                         // [128,16,16,1024]
  float* attn = out + (size_t)B_ * HW_ * C_;           // [128,1024,32]

  const int smem_bytes = HW_ * S_ * 8 + 2 * PC * TC * 4;   // 64 KB + 16 KB = 80 KB
  cudaFuncSetAttribute(attn_kernel, cudaFuncAttributeMaxDynamicSharedMemorySize,
                       smem_bytes);

  we_proj_kernel<<<dim3(4, B_), 256>>>(word_emb, ck, bias);
  attn_kernel<<<dim3(C_ / TC, B_), 256, smem_bytes>>>(wc_in, out, attn);
}

// round 14
// speedup vs baseline: 1.2533x; 1.2533x over previous
#include <cuda_runtime.h>

#define B_   128
#define C_   1024
#define HW_  256
#define S_   32
#define EMB_ 256
#define TC   128    // channels per block (kernel 2)

typedef unsigned long long u64;

// ---- packed f32x2 helpers (sm_103a FFMA2 path) ----
__device__ __forceinline__ u64 pk2(float x, float y) {
  u64 r; asm("mov.b64 %0, {%1, %2};" : "=l"(r) : "f"(x), "f"(y)); return r;
}
__device__ __forceinline__ void upk2(u64 v, float& x, float& y) {
  asm("mov.b64 {%0, %1}, %2;" : "=f"(x), "=f"(y) : "l"(v));
}
__device__ __forceinline__ void fma2(u64& d, u64 a, u64 b) {   // d += a*b (2 lanes)
  asm("fma.rn.f32x2 %0, %1, %2, %0;" : "+l"(d) : "l"(a), "l"(b));
}
__device__ __forceinline__ u64 add2(u64 a, u64 b) {
  u64 r; asm("add.rn.f32x2 %0, %1, %2;" : "=l"(r) : "l"(a), "l"(b)); return r;
}

// we transposed: [b][p][s], 4 MB scratch
__device__ float g_we[(size_t)B_ * HW_ * S_];

// ---------------------------------------------------------------------------
// Kernel 1: we_t[b][p][s] = sum_e word_emb[b][s][e] * ck[e][p] + bias[p]
// Grid (4, B). Coalesced transpose: lane = s, float4 along e, conflict-free STS.
// ---------------------------------------------------------------------------
__global__ __launch_bounds__(256) void we_proj_kernel(
    const float* __restrict__ word_emb,
    const float* __restrict__ ck,
    const float* __restrict__ bias) {
  __shared__ __align__(16) float smem_pool[EMB_ * S_];   // 32 KB
  float (*emb_t)[S_] = (float (*)[S_])smem_pool;          // [e][s]
  u64 (*red)[64][19]  = (u64 (*)[64][19])smem_pool;       // [3][64][19] u64, aliased

  const int b  = blockIdx.y;
  const int ph = blockIdx.x;        // p-quarter 0..3
  const int t  = threadIdx.x;

  const float* wb = word_emb + (size_t)b * S_ * EMB_;
  // transpose-load: lane = s; float4 read along e (16B per lane), STS conflict-free
  {
    const int lane = t & 31;        // = s
    const int w    = t >> 5;        // warp id 0..7
#pragma unroll
    for (int k = 0; k < 8; k++) {
      const int e0 = w * 4 + k * 32;
      float4 v = *(const float4*)&wb[lane * EMB_ + e0];
      emb_t[e0 + 0][lane] = v.x;
      emb_t[e0 + 1][lane] = v.y;
      emb_t[e0 + 2][lane] = v.z;
      emb_t[e0 + 3][lane] = v.w;
    }
  }
  __syncthreads();

  const int p_loc = t & 63;
  const int p     = ph * 64 + p_loc;
  const int eh    = t >> 6;         // e-slice 0..3

  u64 acc2[S_ / 2];
  {
    const u64 init = (eh == 0) ? pk2(bias[p], bias[p]) : 0ull;
#pragma unroll
    for (int q = 0; q < S_ / 2; q++) acc2[q] = init;
  }

#pragma unroll 4
  for (int i = 0; i < EMB_ / 4; i++) {
    const int e = eh * 64 + i;
    const float ckv = ck[e * EMB_ + p];       // coalesced, L2-resident
    const u64 c2 = pk2(ckv, ckv);
    const ulonglong2* er = (const ulonglong2*)emb_t[e];
#pragma unroll
    for (int q = 0; q < 8; q++) {
      ulonglong2 v = er[q];
      fma2(acc2[2*q + 0], v.x, c2);
      fma2(acc2[2*q + 1], v.y, c2);
    }
  }
  __syncthreads();   // all emb_t reads done before red aliases the pool

  if (eh > 0) {
#pragma unroll
    for (int q = 0; q < S_ / 2; q++) red[eh - 1][p_loc][q] = acc2[q];
  }
  __syncthreads();

  if (eh == 0) {
#pragma unroll
    for (int q = 0; q < S_ / 2; q++)
      acc2[q] = add2(add2(acc2[q], red[0][p_loc][q]),
                     add2(red[1][p_loc][q], red[2][p_loc][q]));
    ulonglong2* o = (ulonglong2*)(g_we + ((size_t)b * HW_ + p) * S_);
#pragma unroll
    for (int q = 0; q < 8; q++) {
      ulonglong2 v; v.x = acc2[2*q]; v.y = acc2[2*q + 1];
      o[q] = v;
    }
  }
}

// ---------------------------------------------------------------------------
// Kernel 2 (fused), TC=128, barrier-free logits:
//   logits: wc read DIRECTLY from gmem into registers (warp-private channels,
//           coalesced 64B/warp/row dedup, 8-row register prefetch, ZERO
//           barriers), we from compact smem (1 wavefront/pp).
//   softmax over s (8-lane shuffle groups), attn STG.128 from regs
//   epilogue: 2 channels/thread, broadcast compact we rows
// ---------------------------------------------------------------------------
__global__ __launch_bounds__(256, 2) void attn_kernel(
    const float* __restrict__ wc,
    float* __restrict__ out,
    float* __restrict__ attn_out) {
  __shared__ float we_sm[HW_][S_];        // 32 KB: [p][s] compact
  __shared__ float attn_t[S_][TC];        // 16 KB: [s][c]

  const int b  = blockIdx.y;
  const int c0 = blockIdx.x * TC;
  const int t  = threadIdx.x;

  // stage we_t[b] (8192 floats) into smem
  {
    const float4* gw = (const float4*)(g_we + (size_t)b * HW_ * S_);
    float4* sw = (float4*)we_sm;
    for (int i = t; i < HW_ * S_ / 4; i += 256) sw[i] = gw[i];
  }

  // ---- logits: thread owns channels 4cg..4cg+3, s = 4sg..4sg+3 ----
  const int cg = t >> 3;   // 0..31
  const int sg = t & 7;    // 0..7
  const float* wp = wc + (size_t)b * HW_ * C_ + c0 + cg * 4;  // thread's channel col

  u64 acc2[4][2];          // [channel][s-pair]
#pragma unroll
  for (int i = 0; i < 4; i++) acc2[i][0] = acc2[i][1] = 0ull;

  // prefetch rows 0..7 into registers (independent LDGs, MLP=8)
  float4 w[8];
#pragma unroll
  for (int u = 0; u < 8; u++) w[u] = *(const float4*)(wp + (size_t)u * C_);

  __syncthreads();         // we_sm visible (LDGs above already in flight)

#pragma unroll 1
  for (int p0 = 0; p0 < HW_; p0 += 8) {
    float4 wn[8];
    if (p0 + 8 < HW_) {
#pragma unroll
      for (int u = 0; u < 8; u++)
        wn[u] = *(const float4*)(wp + (size_t)(p0 + 8 + u) * C_);
    }
#pragma unroll
    for (int u = 0; u < 8; u++) {
      ulonglong2 v = *(const ulonglong2*)&we_sm[p0 + u][sg * 4];  // 1 wf/warp
      const u64 w0 = pk2(w[u].x, w[u].x), w1 = pk2(w[u].y, w[u].y);
      const u64 w2 = pk2(w[u].z, w[u].z), w3 = pk2(w[u].w, w[u].w);
      fma2(acc2[0][0], v.x, w0);  fma2(acc2[0][1], v.y, w0);
      fma2(acc2[1][0], v.x, w1);  fma2(acc2[1][1], v.y, w1);
      fma2(acc2[2][0], v.x, w2);  fma2(acc2[2][1], v.y, w2);
      fma2(acc2[3][0], v.x, w3);  fma2(acc2[3][1], v.y, w3);
    }
#pragma unroll
    for (int u = 0; u < 8; u++) w[u] = wn[u];
  }

  // unpack: av[i][j] = logit of channel 4cg+i at s = 4sg+j
  float av[4][4];
#pragma unroll
  for (int i = 0; i < 4; i++) {
    upk2(acc2[i][0], av[i][0], av[i][1]);
    upk2(acc2[i][1], av[i][2], av[i][3]);
  }

  // ---- softmax over s per channel (8-lane aligned shuffle groups) ----
#pragma unroll
  for (int i = 0; i < 4; i++) {
    float m = fmaxf(fmaxf(av[i][0], av[i][1]), fmaxf(av[i][2], av[i][3]));
#pragma unroll
    for (int o = 1; o < 8; o <<= 1) m = fmaxf(m, __shfl_xor_sync(0xffffffffu, m, o));
    float sum = 0.f;
#pragma unroll
    for (int j = 0; j < 4; j++) { av[i][j] = __expf(av[i][j] - m); sum += av[i][j]; }
#pragma unroll
    for (int o = 1; o < 8; o <<= 1) sum += __shfl_xor_sync(0xffffffffu, sum, o);
    const float inv = 1.f / sum;
#pragma unroll
    for (int j = 0; j < 4; j++) av[i][j] *= inv;
  }

  // ---- attn -> gmem straight from registers: attn[b][c][4sg..4sg+3] ----
  {
    float* ab = attn_out + ((size_t)b * C_ + c0 + cg * 4) * S_ + sg * 4;
#pragma unroll
    for (int i = 0; i < 4; i++)
      *(float4*)(ab + (size_t)i * S_) = make_float4(av[i][0], av[i][1], av[i][2], av[i][3]);
  }

  // ---- attn_t[s][c] for the epilogue ----
#pragma unroll
  for (int j = 0; j < 4; j++)
    *(float4*)&attn_t[sg * 4 + j][cg * 4] =
        make_float4(av[0][j], av[1][j], av[2][j], av[3][j]);
  __syncthreads();

  // ---- epilogue: out[b][p][c0+oc(+64)] = sum_s we_sm[p][s] * attn[c][s] ----
  {
    const int oc = t & 63;             // 2 channels: oc, oc+64
    const int pg = t >> 6;             // 0..3 -> 64 p each
    u64 a2a[S_ / 2], a2b[S_ / 2];      // packed attn s-pairs per channel
#pragma unroll
    for (int q = 0; q < S_ / 2; q++) {
      a2a[q] = pk2(attn_t[2*q][oc],      attn_t[2*q + 1][oc]);
      a2b[q] = pk2(attn_t[2*q][oc + 64], attn_t[2*q + 1][oc + 64]);
    }
    float* ob = out + (size_t)b * HW_ * C_ + c0 + oc;
#pragma unroll 2
    for (int k = 0; k < 64; k++) {
      const int p = pg * 64 + k;
      const ulonglong2* wr = (const ulonglong2*)we_sm[p];  // broadcast compact row
      u64 cha[4], chb[4];
#pragma unroll
      for (int q = 0; q < 4; q++) { cha[q] = 0ull; chb[q] = 0ull; }
#pragma unroll
      for (int q4 = 0; q4 < 8; q4++) {
        ulonglong2 v = wr[q4];         // v.x = s(4q4,4q4+1), v.y = s(4q4+2,4q4+3)
        fma2(cha[q4 & 3], v.x, a2a[2*q4 + 0]);
        fma2(cha[q4 & 3], v.y, a2a[2*q4 + 1]);
        fma2(chb[q4 & 3], v.x, a2b[2*q4 + 0]);
        fma2(chb[q4 & 3], v.y, a2b[2*q4 + 1]);
      }
      u64 ra = add2(add2(cha[0], cha[1]), add2(cha[2], cha[3]));
      u64 rb = add2(add2(chb[0], chb[1]), add2(chb[2], chb[3]));
      float lo, hi;
      upk2(ra, lo, hi);
      ob[(size_t)p * C_] = lo + hi;          // coalesced 128B per warp
      upk2(rb, lo, hi);
      ob[(size_t)p * C_ + 64] = lo + hi;
    }
  }
}

// ---------------------------------------------------------------------------
extern "C" void kernel_launch(void* const* d_in, const int* in_sizes, int n_in,
                              void* d_out, int out_size) {
  const float* wc_in    = (const float*)d_in[0];  // weighted_context [128,16,16,1024]
  const float* word_emb = (const float*)d_in[1];  // [128,32,256]
  const float* ck       = (const float*)d_in[2];  // [256,256]
  const float* bias     = (const float*)d_in[3];  // [256]

  float* out  = (float*)d_out;                         // [128,16,16,1024]
  float* attn = out + (size_t)B_ * HW_ * C_;           // [128,1024,32]

  we_proj_kernel<<<dim3(4, B_), 256>>>(word_emb, ck, bias);
  attn_kernel<<<dim3(C_ / TC, B_), 256>>>(wc_in, out, attn);
}